// round 4
// baseline (speedup 1.0000x reference)
#include <cuda_runtime.h>
#include <math.h>

#define H    128
#define SEQ  128
#define BTOT 2048
#define NB   16            // batches per block
#define NBLK (BTOT/NB)     // 128 blocks
#define NTHR 512
#define O5   640           // 512 (W_hh cols) + 128 (W_pq cols), transposed layout

// ---------------- device-global scratch (precomputed once per launch) -------
__device__ float  d_Wt[H*O5];     // Wt[k*640+o] : o<512 -> W_hh[o][k], else W_pq[o-512][k]
__device__ float4 d_A4[H];        // {Ms0, Ms1, w_ld, w_d}
__device__ float  d_cbias[H];     // base bias + b_pq
__device__ float  d_aW[H];
__device__ float  d_G2[512*2];    // W_ih @ W_s
__device__ float  d_gb[512];      // b_ih + b_hh + W_ih@b_s

// ---------------- accurate transcendentals (~1e-9 rel, branch-free) ---------
// e^y via 2^t: Cody-Waite split of y*log2(e), deg-7 Taylor for 2^f on [-.5,.5]
__device__ __forceinline__ float exp_acc(float y) {
    const float L2E_HI = 1.44269502162933349609375f;   // fp32(log2 e)
    const float L2E_LO = 1.9259629911266175e-8f;       // log2(e) - L2E_HI
    float p  = y * L2E_HI;
    float e  = fmaf(y, L2E_HI, -p);                    // exact mul residual
    float pc = fminf(fmaxf(p, -126.0f), 126.0f);
    float nf = rintf(pc);
    int   ni = (int)nf;
    float f  = (pc - nf) + fmaf(y, L2E_LO, e);
    float r  = 1.5252733e-5f;                          // ln2^7/5040
    r = fmaf(r, f, 1.5403530e-4f);                     // ln2^6/720
    r = fmaf(r, f, 1.3333558e-3f);                     // ln2^5/120
    r = fmaf(r, f, 9.6181291e-3f);                     // ln2^4/24
    r = fmaf(r, f, 5.5504109e-2f);                     // ln2^3/6
    r = fmaf(r, f, 2.4022651e-1f);                     // ln2^2/2
    r = fmaf(r, f, 6.9314718e-1f);                     // ln2
    r = fmaf(r, f, 1.0f);
    float sc = __int_as_float((ni + 127) << 23);
    return r * sc;
}
__device__ __forceinline__ float rcp_nr(float d) {
    float r;
    asm("rcp.approx.f32 %0, %1;" : "=f"(r) : "f"(d));
    return r * fmaf(-d, r, 2.0f);                      // one Newton step
}
__device__ __forceinline__ float tanh_acc(float x) {
    float E = exp_acc(x + x);
    float q = rcp_nr(E + 1.0f);
    return 1.0f - (q + q);                             // 1 - 2/(1+e^{2x}); exact subtract
}
__device__ __forceinline__ float sig_acc(float x) {
    return rcp_nr(1.0f + exp_acc(-x));
}

// ---------------- phase 0: fold all the affine algebra (fp64) ---------------
__global__ void precompute_kernel(
    const float* __restrict__ W_s,  const float* __restrict__ b_s,
    const float* __restrict__ W_ld, const float* __restrict__ b_ld,
    const float* __restrict__ W_d,  const float* __restrict__ b_d,
    const float* __restrict__ W_ih, const float* __restrict__ b_ih,
    const float* __restrict__ W_hh, const float* __restrict__ b_hh,
    const float* __restrict__ W_pd, const float* __restrict__ b_pd,
    const float* __restrict__ W_pld,const float* __restrict__ b_pld,
    const float* __restrict__ W_pq, const float* __restrict__ b_pq,
    const float* __restrict__ W_pr, const float* __restrict__ b_pr,
    const float* __restrict__ attn_W)
{
    int tid  = blockIdx.x * blockDim.x + threadIdx.x;
    int nthr = gridDim.x * blockDim.x;

    for (int idx = tid; idx < H*O5; idx += nthr) {
        int k = idx / O5, o = idx % O5;
        d_Wt[idx] = (o < 512) ? W_hh[o*H + k] : W_pq[(o-512)*H + k];
    }
    for (int h = tid; h < H; h += nthr) {
        double ms0=0, ms1=0, wld=0, wd=0, bb=0;
        for (int k = 0; k < H; k++) {
            double wpr  = (double)W_pr [h*H+k];
            double wpld = (double)W_pld[h*H+k];
            double wpd  = (double)W_pd [h*H+k];
            ms0 += wpr  * (double)W_s[k*2+0];
            ms1 += wpr  * (double)W_s[k*2+1];
            wld += wpld * ((double)W_ld[k*2+0] + (double)W_ld[k*2+1]); // size-1 broadcast
            wd  += wpd  * ((double)W_d [k*2+0] + (double)W_d [k*2+1]);
            bb  += wpr*(double)b_s[k] + wpld*(double)b_ld[k] + wpd*(double)b_d[k];
        }
        bb += (double)b_pr[h] + (double)b_pld[h] + (double)b_pd[h] + (double)b_pq[h];
        d_A4[h]    = make_float4((float)ms0, (float)ms1, (float)wld, (float)wd);
        d_cbias[h] = (float)bb;
        d_aW[h]    = attn_W[h];
    }
    for (int o = tid; o < 512; o += nthr) {
        double g0=0, g1=0, gb=0;
        for (int k = 0; k < H; k++) {
            double w = (double)W_ih[o*H+k];
            g0 += w * (double)W_s[k*2+0];
            g1 += w * (double)W_s[k*2+1];
            gb += w * (double)b_s[k];
        }
        d_G2[o*2+0] = (float)g0; d_G2[o*2+1] = (float)g1;
        d_gb[o]     = (float)(gb + (double)b_ih[o] + (double)b_hh[o]);
    }
}

// ---------------- main kernel ------------------------------------------------
struct SmemLayout {
    float4 u[NB][SEQ];
    float4 A4[H];
    float  h[NB][H];
    float  c[NB][H];
    float  qb[NB][H];
    float  gates[NB][512];
    float  G2[512][2];
    float  gb[512];
    float  cbias[H];
    float  aW[H];
    float2 v[NB];
};

extern __shared__ char smem_raw[];

__global__ void __launch_bounds__(NTHR, 1)
drl_main(const float* __restrict__ stat, const float* __restrict__ dyn,
         const float* __restrict__ mark, float* __restrict__ out)
{
    SmemLayout& sm = *reinterpret_cast<SmemLayout*>(smem_raw);
    const int tid = threadIdx.x;
    const int b0  = blockIdx.x * NB;

    for (int i = tid; i < H; i += NTHR) {
        sm.A4[i]    = d_A4[i];
        sm.cbias[i] = d_cbias[i];
        sm.aW[i]    = d_aW[i];
    }
    for (int i = tid; i < 512; i += NTHR) {
        sm.G2[i][0] = d_G2[i*2+0];
        sm.G2[i][1] = d_G2[i*2+1];
        sm.gb[i]    = d_gb[i];
    }
    for (int idx = tid; idx < NB*SEQ; idx += NTHR) {
        int b = idx >> 7, s = idx & 127;
        int g = (b0 + b) * (2*SEQ);
        float s0 = stat[g + s];
        float s1 = stat[g + SEQ + s];
        float ld = dyn [g + s];
        float dm = dyn [g + SEQ + s];
        sm.u[b][s] = make_float4(s0, s1, ld - dm, dm);
    }
    for (int idx = tid; idx < NB*H; idx += NTHR) {
        int b = idx >> 7, j = idx & 127;
        sm.h[b][j] = 0.f;
        sm.c[b][j] = 0.f;
    }
    __syncthreads();
    if (tid < NB) sm.v[tid] = make_float2(sm.u[tid][0].x, sm.u[tid][0].y);
    if (blockIdx.x == 0 && tid == 0) out[2*BTOT*SEQ] = mark[0];
    __syncthreads();

    const int o    = tid;
    const int o2   = tid & 127;
    const int bg   = tid >> 7;
    const int warp = tid >> 5;
    const int lane = tid & 31;
    const float NEG_INF = __int_as_float(0xff800000);

    for (int t = 0; t < SEQ; t++) {
        // ---- GEMM1: gates = h_prev @ W_hh^T + G2@v + gb ----
        {
            float acc[NB];
            float g0 = sm.G2[o][0], g1 = sm.G2[o][1], gbv = sm.gb[o];
            #pragma unroll
            for (int i = 0; i < NB; i++) {
                float2 vv = sm.v[i];
                acc[i] = fmaf(g0, vv.x, fmaf(g1, vv.y, gbv));
            }
            const float* wt = d_Wt + o;
            #pragma unroll 4
            for (int k = 0; k < H; k += 4) {
                float w0 = wt[(k+0)*O5];
                float w1 = wt[(k+1)*O5];
                float w2 = wt[(k+2)*O5];
                float w3 = wt[(k+3)*O5];
                #pragma unroll
                for (int i = 0; i < NB; i++) {
                    float4 hv = *reinterpret_cast<const float4*>(&sm.h[i][k]);
                    acc[i] = fmaf(w0, hv.x, acc[i]);
                    acc[i] = fmaf(w1, hv.y, acc[i]);
                    acc[i] = fmaf(w2, hv.z, acc[i]);
                    acc[i] = fmaf(w3, hv.w, acc[i]);
                }
            }
            #pragma unroll
            for (int i = 0; i < NB; i++) sm.gates[i][o] = acc[i];
        }
        __syncthreads();

        // ---- LSTM pointwise ----
        #pragma unroll
        for (int r = 0; r < (NB*H)/NTHR; r++) {
            int idx = tid + r*NTHR;
            int b = idx >> 7, j = idx & 127;
            float gi = sm.gates[b][j      ];
            float gf = sm.gates[b][j + 128];
            float gg = sm.gates[b][j + 256];
            float go = sm.gates[b][j + 384];
            float c2 = sig_acc(gf) * sm.c[b][j] + sig_acc(gi) * tanh_acc(gg);
            float h2 = sig_acc(go) * tanh_acc(c2);
            sm.c[b][j] = c2;
            sm.h[b][j] = h2;
        }
        __syncthreads();

        // ---- GEMM2: qb = h_new @ W_pq^T + (basebias + b_pq) ----
        {
            float acc[4];
            float cb = sm.cbias[o2];
            #pragma unroll
            for (int j = 0; j < 4; j++) acc[j] = cb;
            const float* wt = d_Wt + 512 + o2;
            #pragma unroll 4
            for (int k = 0; k < H; k += 4) {
                float w0 = wt[(k+0)*O5];
                float w1 = wt[(k+1)*O5];
                float w2 = wt[(k+2)*O5];
                float w3 = wt[(k+3)*O5];
                #pragma unroll
                for (int j = 0; j < 4; j++) {
                    float4 hv = *reinterpret_cast<const float4*>(&sm.h[bg*4+j][k]);
                    acc[j] = fmaf(w0, hv.x, acc[j]);
                    acc[j] = fmaf(w1, hv.y, acc[j]);
                    acc[j] = fmaf(w2, hv.z, acc[j]);
                    acc[j] = fmaf(w3, hv.w, acc[j]);
                }
            }
            #pragma unroll
            for (int j = 0; j < 4; j++) sm.qb[bg*4+j][o2] = acc[j];
        }
        __syncthreads();

        // ---- attention + quantized argmax/softmax (one warp per batch) ----
        {
            const int b = warp;
            float4 uu[4];
            #pragma unroll
            for (int j = 0; j < 4; j++) uu[j] = sm.u[b][lane*4 + j];
            double acc[4] = {0.0, 0.0, 0.0, 0.0};     // fp64 accum kills summation walk
            #pragma unroll 2
            for (int hh = 0; hh < H; hh++) {
                float4 a  = sm.A4[hh];
                float  qh = sm.qb[b][hh];
                float  aw = sm.aW[hh];
                #pragma unroll
                for (int j = 0; j < 4; j++) {
                    float z = fmaf(a.x, uu[j].x,
                              fmaf(a.y, uu[j].y,
                              fmaf(a.z, uu[j].z,
                              fmaf(a.w, uu[j].w, qh))));
                    acc[j] += (double)(aw * tanh_acc(z));
                }
            }
            // REPLICATE reference quantization: logits + 10000.0f in fp32
            // (ulp(10000) = 2^-10 grid; ties broken by FIRST index, like jnp.argmax)
            float aq[4];
            #pragma unroll
            for (int j = 0; j < 4; j++) aq[j] = (float)acc[j] + 10000.0f;
            if (lane == 0) aq[0] = NEG_INF;            // masked slot (prob == 0)

            float m  = aq[0];
            int   mi = lane*4;
            #pragma unroll
            for (int j = 1; j < 4; j++)
                if (aq[j] > m) { m = aq[j]; mi = lane*4 + j; }   // strict > keeps first
            #pragma unroll
            for (int off = 16; off; off >>= 1) {
                float om = __shfl_xor_sync(0xffffffffu, m,  off);
                int   oi = __shfl_xor_sync(0xffffffffu, mi, off);
                if (om > m || (om == m && oi < mi)) { m = om; mi = oi; }
            }
            // softmax denominator on quantized logits (grid-exact differences)
            float dsum = 0.f;
            #pragma unroll
            for (int j = 0; j < 4; j++) {
                float dlt = aq[j] - m;
                dsum += (dlt == NEG_INF) ? 0.f : exp_acc(dlt);
            }
            #pragma unroll
            for (int off = 16; off; off >>= 1)
                dsum += __shfl_xor_sync(0xffffffffu, dsum, off);

            if (lane == 0) {
                out[(b0 + b)*SEQ + t]             = (float)mi;
                out[BTOT*SEQ + (b0 + b)*SEQ + t]  = -logf(dsum);     // log(1/dsum)
                sm.v[b] = make_float2(sm.u[b][mi].x, sm.u[b][mi].y);
            }
        }
        __syncthreads();
    }
}

// ---------------- launch --------------------------------------------------
extern "C" void kernel_launch(void* const* d_in, const int* in_sizes, int n_in,
                              void* d_out, int out_size)
{
    (void)in_sizes; (void)n_in; (void)out_size;
    const float* stat  = (const float*)d_in[0];
    const float* dyn   = (const float*)d_in[1];
    const float* mark  = (const float*)d_in[2];
    const float* W_s   = (const float*)d_in[3];
    const float* b_s   = (const float*)d_in[4];
    const float* W_ld  = (const float*)d_in[5];
    const float* b_ld  = (const float*)d_in[6];
    const float* W_d   = (const float*)d_in[7];
    const float* b_d   = (const float*)d_in[8];
    const float* W_ih  = (const float*)d_in[9];
    const float* b_ih  = (const float*)d_in[10];
    const float* W_hh  = (const float*)d_in[11];
    const float* b_hh  = (const float*)d_in[12];
    const float* W_pd  = (const float*)d_in[13];
    const float* b_pd  = (const float*)d_in[14];
    const float* W_pld = (const float*)d_in[15];
    const float* b_pld = (const float*)d_in[16];
    const float* W_pq  = (const float*)d_in[17];
    const float* b_pq  = (const float*)d_in[18];
    const float* W_pr  = (const float*)d_in[19];
    const float* b_pr  = (const float*)d_in[20];
    const float* attn_W= (const float*)d_in[21];
    float* out = (float*)d_out;

    cudaFuncSetAttribute(drl_main, cudaFuncAttributeMaxDynamicSharedMemorySize,
                         (int)sizeof(SmemLayout));

    precompute_kernel<<<84, 512>>>(W_s, b_s, W_ld, b_ld, W_d, b_d,
                                   W_ih, b_ih, W_hh, b_hh,
                                   W_pd, b_pd, W_pld, b_pld,
                                   W_pq, b_pq, W_pr, b_pr, attn_W);

    drl_main<<<NBLK, NTHR, sizeof(SmemLayout)>>>(stat, dyn, mark, out);
}

// round 7
// speedup vs baseline: 1.0107x; 1.0107x over previous
#include <cuda_runtime.h>
#include <math.h>

#define H    128
#define SEQ  128
#define BTOT 2048
#define NB   8             // batches per block (halved -> 2 CTAs/SM)
#define NBLK (BTOT/NB)     // 256 blocks
#define NTHR 512
#define O5   640           // 512 (W_hh cols) + 128 (W_pq cols), transposed layout

// ---------------- device-global scratch (precomputed once per launch) -------
__device__ float  d_Wt[H*O5];     // Wt[k*640+o] : o<512 -> W_hh[o][k], else W_pq[o-512][k]
__device__ float4 d_A4[H];        // {Ms0, Ms1, w_ld, w_d}
__device__ float  d_cbias[H];     // base bias + b_pq
__device__ float  d_aW[H];
__device__ float  d_G2[512*2];    // W_ih @ W_s
__device__ float  d_gb[512];      // b_ih + b_hh + W_ih@b_s

// ---------------- accurate transcendentals (~1e-9 rel) — BITWISE same as R4 -
__device__ __forceinline__ float exp_acc(float y) {
    const float L2E_HI = 1.44269502162933349609375f;
    const float L2E_LO = 1.9259629911266175e-8f;
    float p  = y * L2E_HI;
    float e  = fmaf(y, L2E_HI, -p);
    float pc = fminf(fmaxf(p, -126.0f), 126.0f);
    float nf = rintf(pc);
    int   ni = (int)nf;
    float f  = (pc - nf) + fmaf(y, L2E_LO, e);
    float r  = 1.5252733e-5f;
    r = fmaf(r, f, 1.5403530e-4f);
    r = fmaf(r, f, 1.3333558e-3f);
    r = fmaf(r, f, 9.6181291e-3f);
    r = fmaf(r, f, 5.5504109e-2f);
    r = fmaf(r, f, 2.4022651e-1f);
    r = fmaf(r, f, 6.9314718e-1f);
    r = fmaf(r, f, 1.0f);
    float sc = __int_as_float((ni + 127) << 23);
    return r * sc;
}
__device__ __forceinline__ float rcp_nr(float d) {
    float r;
    asm("rcp.approx.f32 %0, %1;" : "=f"(r) : "f"(d));
    return r * fmaf(-d, r, 2.0f);
}
__device__ __forceinline__ float tanh_acc(float x) {
    float E = exp_acc(x + x);
    float q = rcp_nr(E + 1.0f);
    return 1.0f - (q + q);
}
__device__ __forceinline__ float sig_acc(float x) {
    return rcp_nr(1.0f + exp_acc(-x));
}

// ---------------- phase 0: fold all the affine algebra (fp64) ---------------
__global__ void precompute_kernel(
    const float* __restrict__ W_s,  const float* __restrict__ b_s,
    const float* __restrict__ W_ld, const float* __restrict__ b_ld,
    const float* __restrict__ W_d,  const float* __restrict__ b_d,
    const float* __restrict__ W_ih, const float* __restrict__ b_ih,
    const float* __restrict__ W_hh, const float* __restrict__ b_hh,
    const float* __restrict__ W_pd, const float* __restrict__ b_pd,
    const float* __restrict__ W_pld,const float* __restrict__ b_pld,
    const float* __restrict__ W_pq, const float* __restrict__ b_pq,
    const float* __restrict__ W_pr, const float* __restrict__ b_pr,
    const float* __restrict__ attn_W)
{
    int tid  = blockIdx.x * blockDim.x + threadIdx.x;
    int nthr = gridDim.x * blockDim.x;

    for (int idx = tid; idx < H*O5; idx += nthr) {
        int k = idx / O5, o = idx % O5;
        d_Wt[idx] = (o < 512) ? W_hh[o*H + k] : W_pq[(o-512)*H + k];
    }
    for (int h = tid; h < H; h += nthr) {
        double ms0=0, ms1=0, wld=0, wd=0, bb=0;
        for (int k = 0; k < H; k++) {
            double wpr  = (double)W_pr [h*H+k];
            double wpld = (double)W_pld[h*H+k];
            double wpd  = (double)W_pd [h*H+k];
            ms0 += wpr  * (double)W_s[k*2+0];
            ms1 += wpr  * (double)W_s[k*2+1];
            wld += wpld * ((double)W_ld[k*2+0] + (double)W_ld[k*2+1]);
            wd  += wpd  * ((double)W_d [k*2+0] + (double)W_d [k*2+1]);
            bb  += wpr*(double)b_s[k] + wpld*(double)b_ld[k] + wpd*(double)b_d[k];
        }
        bb += (double)b_pr[h] + (double)b_pld[h] + (double)b_pd[h] + (double)b_pq[h];
        d_A4[h]    = make_float4((float)ms0, (float)ms1, (float)wld, (float)wd);
        d_cbias[h] = (float)bb;
        d_aW[h]    = attn_W[h];
    }
    for (int o = tid; o < 512; o += nthr) {
        double g0=0, g1=0, gb=0;
        for (int k = 0; k < H; k++) {
            double w = (double)W_ih[o*H+k];
            g0 += w * (double)W_s[k*2+0];
            g1 += w * (double)W_s[k*2+1];
            gb += w * (double)b_s[k];
        }
        d_G2[o*2+0] = (float)g0; d_G2[o*2+1] = (float)g1;
        d_gb[o]     = (float)(gb + (double)b_ih[o] + (double)b_hh[o]);
    }
}

// ---------------- main kernel ------------------------------------------------
struct SmemLayout {
    float4 u[NB][SEQ];       // 16KB
    float4 A4[H];            //  2KB
    float  h[NB][H];         //  4KB
    float  c[NB][H];         //  4KB
    float  qb[NB][H];        //  4KB
    float  gates[NB][512];   // 16KB
    float  G2[512][2];       //  4KB
    float  gb[512];          //  2KB
    float  cbias[H];
    float  aW[H];
    float2 v[NB];
    float  red_m [NB][2];    // per-half argmax value
    int    red_mi[NB][2];    // per-half argmax index
    float  red_ds[NB][2];    // per-half softmax partial (rel. to half max)
};

extern __shared__ char smem_raw[];

__global__ void __launch_bounds__(NTHR, 2)
drl_main(const float* __restrict__ stat, const float* __restrict__ dyn,
         const float* __restrict__ mark, float* __restrict__ out)
{
    SmemLayout& sm = *reinterpret_cast<SmemLayout*>(smem_raw);
    const int tid = threadIdx.x;
    const int b0  = blockIdx.x * NB;

    for (int i = tid; i < H; i += NTHR) {
        sm.A4[i]    = d_A4[i];
        sm.cbias[i] = d_cbias[i];
        sm.aW[i]    = d_aW[i];
    }
    for (int i = tid; i < 512; i += NTHR) {
        sm.G2[i][0] = d_G2[i*2+0];
        sm.G2[i][1] = d_G2[i*2+1];
        sm.gb[i]    = d_gb[i];
    }
    for (int idx = tid; idx < NB*SEQ; idx += NTHR) {
        int b = idx >> 7, s = idx & 127;
        int g = (b0 + b) * (2*SEQ);
        float s0 = stat[g + s];
        float s1 = stat[g + SEQ + s];
        float ld = dyn [g + s];
        float dm = dyn [g + SEQ + s];
        sm.u[b][s] = make_float4(s0, s1, ld - dm, dm);
    }
    for (int idx = tid; idx < NB*H; idx += NTHR) {
        int b = idx >> 7, j = idx & 127;
        sm.h[b][j] = 0.f;
        sm.c[b][j] = 0.f;
    }
    __syncthreads();
    if (tid < NB) sm.v[tid] = make_float2(sm.u[tid][0].x, sm.u[tid][0].y);
    if (blockIdx.x == 0 && tid == 0) out[2*BTOT*SEQ] = mark[0];
    __syncthreads();

    const int o    = tid;          // GEMM1 output column (0..511)
    const int o2   = tid & 127;    // GEMM2 output column
    const int bg   = tid >> 7;     // GEMM2 batch group (0..3), 2 batches each
    const int warp = tid >> 5;     // attention: 2 warps per batch
    const int lane = tid & 31;
    const int ab   = warp >> 1;    // attention batch
    const int ah   = warp & 1;     // attention s-half
    const float NEG_INF = __int_as_float(0xff800000);

    for (int t = 0; t < SEQ; t++) {
        // ---- GEMM1: gates = h_prev @ W_hh^T + G2@v + gb (k-order as R4) ----
        {
            float acc[NB];
            float g0 = sm.G2[o][0], g1 = sm.G2[o][1], gbv = sm.gb[o];
            #pragma unroll
            for (int i = 0; i < NB; i++) {
                float2 vv = sm.v[i];
                acc[i] = fmaf(g0, vv.x, fmaf(g1, vv.y, gbv));
            }
            const float* wt = d_Wt + o;
            #pragma unroll 4
            for (int k = 0; k < H; k += 4) {
                float w0 = wt[(k+0)*O5];
                float w1 = wt[(k+1)*O5];
                float w2 = wt[(k+2)*O5];
                float w3 = wt[(k+3)*O5];
                #pragma unroll
                for (int i = 0; i < NB; i++) {
                    float4 hv = *reinterpret_cast<const float4*>(&sm.h[i][k]);
                    acc[i] = fmaf(w0, hv.x, acc[i]);
                    acc[i] = fmaf(w1, hv.y, acc[i]);
                    acc[i] = fmaf(w2, hv.z, acc[i]);
                    acc[i] = fmaf(w3, hv.w, acc[i]);
                }
            }
            #pragma unroll
            for (int i = 0; i < NB; i++) sm.gates[i][o] = acc[i];
        }
        __syncthreads();

        // ---- LSTM pointwise (identical math) ----
        #pragma unroll
        for (int r = 0; r < (NB*H)/NTHR; r++) {
            int idx = tid + r*NTHR;
            int b = idx >> 7, j = idx & 127;
            float gi = sm.gates[b][j      ];
            float gf = sm.gates[b][j + 128];
            float gg = sm.gates[b][j + 256];
            float go = sm.gates[b][j + 384];
            float c2 = sig_acc(gf) * sm.c[b][j] + sig_acc(gi) * tanh_acc(gg);
            float h2 = sig_acc(go) * tanh_acc(c2);
            sm.c[b][j] = c2;
            sm.h[b][j] = h2;
        }
        __syncthreads();

        // ---- GEMM2: qb = h_new @ W_pq^T + cbias (2 batches per group) ----
        {
            float acc[2];
            float cb = sm.cbias[o2];
            acc[0] = cb; acc[1] = cb;
            const float* wt = d_Wt + 512 + o2;
            #pragma unroll 4
            for (int k = 0; k < H; k += 4) {
                float w0 = wt[(k+0)*O5];
                float w1 = wt[(k+1)*O5];
                float w2 = wt[(k+2)*O5];
                float w3 = wt[(k+3)*O5];
                #pragma unroll
                for (int j = 0; j < 2; j++) {
                    float4 hv = *reinterpret_cast<const float4*>(&sm.h[bg*2+j][k]);
                    acc[j] = fmaf(w0, hv.x, acc[j]);
                    acc[j] = fmaf(w1, hv.y, acc[j]);
                    acc[j] = fmaf(w2, hv.z, acc[j]);
                    acc[j] = fmaf(w3, hv.w, acc[j]);
                }
            }
            #pragma unroll
            for (int j = 0; j < 2; j++) sm.qb[bg*2+j][o2] = acc[j];
        }
        __syncthreads();

        // ---- attention: 2 warps/batch, bitwise-identical per-s math ----
        {
            const int b     = ab;
            const int sbase = ah*64 + lane*2;
            float4 uu[2];
            #pragma unroll
            for (int j = 0; j < 2; j++) uu[j] = sm.u[b][sbase + j];
            double acc[2] = {0.0, 0.0};
            #pragma unroll 2
            for (int hh = 0; hh < H; hh++) {
                float4 a  = sm.A4[hh];
                float  qh = sm.qb[b][hh];
                float  aw = sm.aW[hh];
                #pragma unroll
                for (int j = 0; j < 2; j++) {
                    float z = fmaf(a.x, uu[j].x,
                              fmaf(a.y, uu[j].y,
                              fmaf(a.z, uu[j].z,
                              fmaf(a.w, uu[j].w, qh))));
                    acc[j] += (double)(aw * tanh_acc(z));
                }
            }
            // quantize exactly like reference: + 10000.0f in fp32
            float aq[2];
            #pragma unroll
            for (int j = 0; j < 2; j++) aq[j] = (float)acc[j] + 10000.0f;
            if (ah == 0 && lane == 0) aq[0] = NEG_INF;   // masked s=0

            // per-half argmax with first-index tie-break
            float m  = aq[0];
            int   mi = sbase;
            if (aq[1] > m) { m = aq[1]; mi = sbase + 1; }
            #pragma unroll
            for (int off = 16; off; off >>= 1) {
                float om = __shfl_xor_sync(0xffffffffu, m,  off);
                int   oi = __shfl_xor_sync(0xffffffffu, mi, off);
                if (om > m || (om == m && oi < mi)) { m = om; mi = oi; }
            }
            // per-half softmax partial relative to half max
            float dsum = 0.f;
            #pragma unroll
            for (int j = 0; j < 2; j++) {
                float dlt = aq[j] - m;
                dsum += (dlt == NEG_INF) ? 0.f : exp_acc(dlt);
            }
            #pragma unroll
            for (int off = 16; off; off >>= 1)
                dsum += __shfl_xor_sync(0xffffffffu, dsum, off);

            if (lane == 0) {
                sm.red_m [b][ah] = m;
                sm.red_mi[b][ah] = mi;
                sm.red_ds[b][ah] = dsum;
            }
        }
        __syncthreads();

        // ---- combine halves, emit outputs, update dec ----
        if (tid < NB) {
            const int b = tid;
            float m0 = sm.red_m[b][0], m1 = sm.red_m[b][1];
            int  mi0 = sm.red_mi[b][0], mi1 = sm.red_mi[b][1];
            float d0 = sm.red_ds[b][0], d1 = sm.red_ds[b][1];
            float m; int mi;
            if (m1 > m0 || (m1 == m0 && mi1 < mi0)) { m = m1; mi = mi1; }
            else                                    { m = m0; mi = mi0; }
            float dsum = d0 * exp_acc(m0 - m) + d1 * exp_acc(m1 - m);
            out[(b0 + b)*SEQ + t]            = (float)mi;
            out[BTOT*SEQ + (b0 + b)*SEQ + t] = -logf(dsum);
            sm.v[b] = make_float2(sm.u[b][mi].x, sm.u[b][mi].y);
        }
        __syncthreads();
    }
}

// ---------------- launch --------------------------------------------------
extern "C" void kernel_launch(void* const* d_in, const int* in_sizes, int n_in,
                              void* d_out, int out_size)
{
    (void)in_sizes; (void)n_in; (void)out_size;
    const float* stat  = (const float*)d_in[0];
    const float* dyn   = (const float*)d_in[1];
    const float* mark  = (const float*)d_in[2];
    const float* W_s   = (const float*)d_in[3];
    const float* b_s   = (const float*)d_in[4];
    const float* W_ld  = (const float*)d_in[5];
    const float* b_ld  = (const float*)d_in[6];
    const float* W_d   = (const float*)d_in[7];
    const float* b_d   = (const float*)d_in[8];
    const float* W_ih  = (const float*)d_in[9];
    const float* b_ih  = (const float*)d_in[10];
    const float* W_hh  = (const float*)d_in[11];
    const float* b_hh  = (const float*)d_in[12];
    const float* W_pd  = (const float*)d_in[13];
    const float* b_pd  = (const float*)d_in[14];
    const float* W_pld = (const float*)d_in[15];
    const float* b_pld = (const float*)d_in[16];
    const float* W_pq  = (const float*)d_in[17];
    const float* b_pq  = (const float*)d_in[18];
    const float* W_pr  = (const float*)d_in[19];
    const float* b_pr  = (const float*)d_in[20];
    const float* attn_W= (const float*)d_in[21];
    float* out = (float*)d_out;

    cudaFuncSetAttribute(drl_main, cudaFuncAttributeMaxDynamicSharedMemorySize,
                         (int)sizeof(SmemLayout));

    precompute_kernel<<<84, 512>>>(W_s, b_s, W_ld, b_ld, W_d, b_d,
                                   W_ih, b_ih, W_hh, b_hh,
                                   W_pd, b_pd, W_pld, b_pld,
                                   W_pq, b_pq, W_pr, b_pr, attn_W);

    drl_main<<<NBLK, NTHR, sizeof(SmemLayout)>>>(stat, dyn, mark, out);
}

// round 8
// speedup vs baseline: 3.5987x; 3.5606x over previous
#include <cuda_runtime.h>
#include <math.h>

#define H    128
#define SEQ  128
#define BTOT 2048
#define NB   8             // batches per block
#define NBLK (BTOT/NB)     // 256 blocks
#define NTHR 512
#define O5   640           // 512 (W_hh cols) + 128 (W_pq cols), transposed layout

// ---------------- device-global scratch (precomputed once per launch) -------
__device__ float  d_Wt[H*O5];
__device__ float4 d_A4[H];
__device__ float  d_cbias[H];
__device__ float  d_aW[H];
__device__ float  d_G2[512*2];
__device__ float  d_gb[512];

// ---------------- exact transcendentals (R4-bitwise, used for LSTM + candidates)
__device__ __forceinline__ float exp_acc(float y) {
    const float L2E_HI = 1.44269502162933349609375f;
    const float L2E_LO = 1.9259629911266175e-8f;
    float p  = y * L2E_HI;
    float e  = fmaf(y, L2E_HI, -p);
    float pc = fminf(fmaxf(p, -126.0f), 126.0f);
    float nf = rintf(pc);
    int   ni = (int)nf;
    float f  = (pc - nf) + fmaf(y, L2E_LO, e);
    float r  = 1.5252733e-5f;
    r = fmaf(r, f, 1.5403530e-4f);
    r = fmaf(r, f, 1.3333558e-3f);
    r = fmaf(r, f, 9.6181291e-3f);
    r = fmaf(r, f, 5.5504109e-2f);
    r = fmaf(r, f, 2.4022651e-1f);
    r = fmaf(r, f, 6.9314718e-1f);
    r = fmaf(r, f, 1.0f);
    float sc = __int_as_float((ni + 127) << 23);
    return r * sc;
}
__device__ __forceinline__ float rcp_nr(float d) {
    float r;
    asm("rcp.approx.f32 %0, %1;" : "=f"(r) : "f"(d));
    return r * fmaf(-d, r, 2.0f);
}
__device__ __forceinline__ float tanh_acc(float x) {
    float E = exp_acc(x + x);
    float q = rcp_nr(E + 1.0f);
    return 1.0f - (q + q);
}
__device__ __forceinline__ float sig_acc(float x) {
    return rcp_nr(1.0f + exp_acc(-x));
}
// cheap HW tanh (MUFU.TANH, abs err ~1e-3) for the bulk attention pass
__device__ __forceinline__ float tanh_fast(float x) {
    float y;
    asm("tanh.approx.f32 %0, %1;" : "=f"(y) : "f"(x));
    return y;
}

// ---------------- phase 0: fold all the affine algebra (fp64) ---------------
__global__ void precompute_kernel(
    const float* __restrict__ W_s,  const float* __restrict__ b_s,
    const float* __restrict__ W_ld, const float* __restrict__ b_ld,
    const float* __restrict__ W_d,  const float* __restrict__ b_d,
    const float* __restrict__ W_ih, const float* __restrict__ b_ih,
    const float* __restrict__ W_hh, const float* __restrict__ b_hh,
    const float* __restrict__ W_pd, const float* __restrict__ b_pd,
    const float* __restrict__ W_pld,const float* __restrict__ b_pld,
    const float* __restrict__ W_pq, const float* __restrict__ b_pq,
    const float* __restrict__ W_pr, const float* __restrict__ b_pr,
    const float* __restrict__ attn_W)
{
    int tid  = blockIdx.x * blockDim.x + threadIdx.x;
    int nthr = gridDim.x * blockDim.x;

    for (int idx = tid; idx < H*O5; idx += nthr) {
        int k = idx / O5, o = idx % O5;
        d_Wt[idx] = (o < 512) ? W_hh[o*H + k] : W_pq[(o-512)*H + k];
    }
    for (int h = tid; h < H; h += nthr) {
        double ms0=0, ms1=0, wld=0, wd=0, bb=0;
        for (int k = 0; k < H; k++) {
            double wpr  = (double)W_pr [h*H+k];
            double wpld = (double)W_pld[h*H+k];
            double wpd  = (double)W_pd [h*H+k];
            ms0 += wpr  * (double)W_s[k*2+0];
            ms1 += wpr  * (double)W_s[k*2+1];
            wld += wpld * ((double)W_ld[k*2+0] + (double)W_ld[k*2+1]);
            wd  += wpd  * ((double)W_d [k*2+0] + (double)W_d [k*2+1]);
            bb  += wpr*(double)b_s[k] + wpld*(double)b_ld[k] + wpd*(double)b_d[k];
        }
        bb += (double)b_pr[h] + (double)b_pld[h] + (double)b_pd[h] + (double)b_pq[h];
        d_A4[h]    = make_float4((float)ms0, (float)ms1, (float)wld, (float)wd);
        d_cbias[h] = (float)bb;
        d_aW[h]    = attn_W[h];
    }
    for (int o = tid; o < 512; o += nthr) {
        double g0=0, g1=0, gb=0;
        for (int k = 0; k < H; k++) {
            double w = (double)W_ih[o*H+k];
            g0 += w * (double)W_s[k*2+0];
            g1 += w * (double)W_s[k*2+1];
            gb += w * (double)b_s[k];
        }
        d_G2[o*2+0] = (float)g0; d_G2[o*2+1] = (float)g1;
        d_gb[o]     = (float)(gb + (double)b_ih[o] + (double)b_hh[o]);
    }
}

// ---------------- main kernel ------------------------------------------------
struct SmemLayout {
    float4 u[NB][SEQ];       // 16KB
    float4 A4[H];            //  2KB
    float  h[NB][H];         //  4KB
    float  c[NB][H];         //  4KB
    float2 qa[NB][H];        //  8KB  {q + cbias, aW}
    float  gates[NB][512];   // 16KB
    float  G2[512][2];       //  4KB
    float  gb[512];          //  2KB
    float  cbias[H];
    float  aW[H];
    float2 v[NB];
    float  red_m [NB][2];
    int    red_mi[NB][2];
    float  red_ds[NB][2];
};

extern __shared__ char smem_raw[];

__global__ void __launch_bounds__(NTHR, 2)
drl_main(const float* __restrict__ stat, const float* __restrict__ dyn,
         const float* __restrict__ mark, float* __restrict__ out)
{
    SmemLayout& sm = *reinterpret_cast<SmemLayout*>(smem_raw);
    const int tid = threadIdx.x;
    const int b0  = blockIdx.x * NB;

    for (int i = tid; i < H; i += NTHR) {
        sm.A4[i]    = d_A4[i];
        sm.cbias[i] = d_cbias[i];
        sm.aW[i]    = d_aW[i];
    }
    for (int i = tid; i < 512; i += NTHR) {
        sm.G2[i][0] = d_G2[i*2+0];
        sm.G2[i][1] = d_G2[i*2+1];
        sm.gb[i]    = d_gb[i];
    }
    for (int idx = tid; idx < NB*SEQ; idx += NTHR) {
        int b = idx >> 7, s = idx & 127;
        int g = (b0 + b) * (2*SEQ);
        float s0 = stat[g + s];
        float s1 = stat[g + SEQ + s];
        float ld = dyn [g + s];
        float dm = dyn [g + SEQ + s];
        sm.u[b][s] = make_float4(s0, s1, ld - dm, dm);
    }
    for (int idx = tid; idx < NB*H; idx += NTHR) {
        int b = idx >> 7, j = idx & 127;
        sm.h[b][j] = 0.f;
        sm.c[b][j] = 0.f;
    }
    __syncthreads();
    if (tid < NB) sm.v[tid] = make_float2(sm.u[tid][0].x, sm.u[tid][0].y);
    if (blockIdx.x == 0 && tid == 0) out[2*BTOT*SEQ] = mark[0];
    __syncthreads();

    const int o    = tid;
    const int o2   = tid & 127;
    const int bg   = tid >> 7;
    const int warp = tid >> 5;
    const int lane = tid & 31;
    const int ab   = warp >> 1;    // attention batch (2 warps/batch)
    const int ah   = warp & 1;     // attention s-half
    const float NEG_INF = __int_as_float(0xff800000);
    const float MARGIN  = 0.012f;  // covers worst-case cheap-tanh bias + tie cell

    for (int t = 0; t < SEQ; t++) {
        // ---- GEMM1: gates = h_prev @ W_hh^T + G2@v + gb (R4-bitwise) ----
        {
            float acc[NB];
            float g0 = sm.G2[o][0], g1 = sm.G2[o][1], gbv = sm.gb[o];
            #pragma unroll
            for (int i = 0; i < NB; i++) {
                float2 vv = sm.v[i];
                acc[i] = fmaf(g0, vv.x, fmaf(g1, vv.y, gbv));
            }
            const float* wt = d_Wt + o;
            #pragma unroll 4
            for (int k = 0; k < H; k += 4) {
                float w0 = wt[(k+0)*O5];
                float w1 = wt[(k+1)*O5];
                float w2 = wt[(k+2)*O5];
                float w3 = wt[(k+3)*O5];
                #pragma unroll
                for (int i = 0; i < NB; i++) {
                    float4 hv = *reinterpret_cast<const float4*>(&sm.h[i][k]);
                    acc[i] = fmaf(w0, hv.x, acc[i]);
                    acc[i] = fmaf(w1, hv.y, acc[i]);
                    acc[i] = fmaf(w2, hv.z, acc[i]);
                    acc[i] = fmaf(w3, hv.w, acc[i]);
                }
            }
            #pragma unroll
            for (int i = 0; i < NB; i++) sm.gates[i][o] = acc[i];
        }
        __syncthreads();

        // ---- LSTM pointwise (R4-bitwise) ----
        #pragma unroll
        for (int r = 0; r < (NB*H)/NTHR; r++) {
            int idx = tid + r*NTHR;
            int b = idx >> 7, j = idx & 127;
            float gi = sm.gates[b][j      ];
            float gf = sm.gates[b][j + 128];
            float gg = sm.gates[b][j + 256];
            float go = sm.gates[b][j + 384];
            float c2 = sig_acc(gf) * sm.c[b][j] + sig_acc(gi) * tanh_acc(gg);
            float h2 = sig_acc(go) * tanh_acc(c2);
            sm.c[b][j] = c2;
            sm.h[b][j] = h2;
        }
        __syncthreads();

        // ---- GEMM2: qa = {h_new @ W_pq^T + cbias, aW} ----
        {
            float acc[2];
            float cb = sm.cbias[o2];
            acc[0] = cb; acc[1] = cb;
            const float* wt = d_Wt + 512 + o2;
            #pragma unroll 4
            for (int k = 0; k < H; k += 4) {
                float w0 = wt[(k+0)*O5];
                float w1 = wt[(k+1)*O5];
                float w2 = wt[(k+2)*O5];
                float w3 = wt[(k+3)*O5];
                #pragma unroll
                for (int j = 0; j < 2; j++) {
                    float4 hv = *reinterpret_cast<const float4*>(&sm.h[bg*2+j][k]);
                    acc[j] = fmaf(w0, hv.x, acc[j]);
                    acc[j] = fmaf(w1, hv.y, acc[j]);
                    acc[j] = fmaf(w2, hv.z, acc[j]);
                    acc[j] = fmaf(w3, hv.w, acc[j]);
                }
            }
            float aw = sm.aW[o2];
            #pragma unroll
            for (int j = 0; j < 2; j++)
                sm.qa[bg*2+j][o2] = make_float2(acc[j], aw);
        }
        __syncthreads();

        // ---- attention: cheap MUFU pass + exact candidate recompute ----
        {
            const int b     = ab;
            const int sbase = ah*64 + lane*2;
            float4 u0 = sm.u[b][sbase];
            float4 u1 = sm.u[b][sbase + 1];
            float c0 = 0.f, c1 = 0.f;
            #pragma unroll 4
            for (int hh = 0; hh < H; hh++) {
                float4 a  = sm.A4[hh];
                float2 qa = sm.qa[b][hh];
                float z0 = fmaf(a.x,u0.x, fmaf(a.y,u0.y, fmaf(a.z,u0.z, fmaf(a.w,u0.w, qa.x))));
                float z1 = fmaf(a.x,u1.x, fmaf(a.y,u1.y, fmaf(a.z,u1.z, fmaf(a.w,u1.w, qa.x))));
                c0 = fmaf(qa.y, tanh_fast(z0), c0);
                c1 = fmaf(qa.y, tanh_fast(z1), c1);
            }
            if (ah == 0 && lane == 0) c0 = NEG_INF;   // masked s=0

            // warp-wide cheap max (value only)
            float cm = fmaxf(c0, c1);
            #pragma unroll
            for (int off = 16; off; off >>= 1)
                cm = fmaxf(cm, __shfl_xor_sync(0xffffffffu, cm, off));

            // candidate masks (true argmax + all its quantized ties provably inside)
            unsigned bal0 = __ballot_sync(0xffffffffu, c0 >= cm - MARGIN);
            unsigned bal1 = __ballot_sync(0xffffffffu, c1 >= cm - MARGIN);

            // exact recompute: warp-cooperative, fp64, deterministic tree
            #pragma unroll
            for (int j = 0; j < 2; j++) {
                unsigned msk = j ? bal1 : bal0;
                while (msk) {
                    int sl = __ffs(msk) - 1;
                    msk &= msk - 1;
                    int s = ah*64 + sl*2 + j;
                    float4 us = sm.u[b][s];
                    double p = 0.0;
                    #pragma unroll
                    for (int r = 0; r < 4; r++) {
                        int hh = lane + r*32;
                        float4 a  = sm.A4[hh];
                        float2 qa = sm.qa[b][hh];
                        float z = fmaf(a.x,us.x, fmaf(a.y,us.y, fmaf(a.z,us.z, fmaf(a.w,us.w, qa.x))));
                        p += (double)(qa.y * tanh_acc(z));
                    }
                    #pragma unroll
                    for (int off = 16; off; off >>= 1)
                        p += __shfl_xor_sync(0xffffffffu, p, off);
                    if (lane == sl) { if (j) c1 = (float)p; else c0 = (float)p; }
                }
            }

            // quantize like reference (+10000.0f fp32; ulp grid 2^-10)
            float aq0 = c0 + 10000.0f;    // -inf stays -inf
            float aq1 = c1 + 10000.0f;

            // per-half argmax, first-index tie-break
            float m  = aq0;
            int   mi = sbase;
            if (aq1 > m) { m = aq1; mi = sbase + 1; }
            #pragma unroll
            for (int off = 16; off; off >>= 1) {
                float om = __shfl_xor_sync(0xffffffffu, m,  off);
                int   oi = __shfl_xor_sync(0xffffffffu, mi, off);
                if (om > m || (om == m && oi < mi)) { m = om; mi = oi; }
            }
            // per-half softmax partial (accurate exp; cheap-logit noise ~1e-4)
            float d0 = aq0 - m, d1 = aq1 - m;
            float dsum = ((d0 == NEG_INF) ? 0.f : exp_acc(d0))
                       + ((d1 == NEG_INF) ? 0.f : exp_acc(d1));
            #pragma unroll
            for (int off = 16; off; off >>= 1)
                dsum += __shfl_xor_sync(0xffffffffu, dsum, off);

            if (lane == 0) {
                sm.red_m [b][ah] = m;
                sm.red_mi[b][ah] = mi;
                sm.red_ds[b][ah] = dsum;
            }
        }
        __syncthreads();

        // ---- combine halves, emit outputs, update dec ----
        if (tid < NB) {
            const int b = tid;
            float m0 = sm.red_m[b][0], m1 = sm.red_m[b][1];
            int  mi0 = sm.red_mi[b][0], mi1 = sm.red_mi[b][1];
            float dd0 = sm.red_ds[b][0], dd1 = sm.red_ds[b][1];
            float m; int mi;
            if (m1 > m0 || (m1 == m0 && mi1 < mi0)) { m = m1; mi = mi1; }
            else                                    { m = m0; mi = mi0; }
            float dsum = dd0 * exp_acc(m0 - m) + dd1 * exp_acc(m1 - m);
            out[(b0 + b)*SEQ + t]            = (float)mi;
            out[BTOT*SEQ + (b0 + b)*SEQ + t] = -logf(dsum);
            sm.v[b] = make_float2(sm.u[b][mi].x, sm.u[b][mi].y);
        }
        __syncthreads();
    }
}

// ---------------- launch --------------------------------------------------
extern "C" void kernel_launch(void* const* d_in, const int* in_sizes, int n_in,
                              void* d_out, int out_size)
{
    (void)in_sizes; (void)n_in; (void)out_size;
    const float* stat  = (const float*)d_in[0];
    const float* dyn   = (const float*)d_in[1];
    const float* mark  = (const float*)d_in[2];
    const float* W_s   = (const float*)d_in[3];
    const float* b_s   = (const float*)d_in[4];
    const float* W_ld  = (const float*)d_in[5];
    const float* b_ld  = (const float*)d_in[6];
    const float* W_d   = (const float*)d_in[7];
    const float* b_d   = (const float*)d_in[8];
    const float* W_ih  = (const float*)d_in[9];
    const float* b_ih  = (const float*)d_in[10];
    const float* W_hh  = (const float*)d_in[11];
    const float* b_hh  = (const float*)d_in[12];
    const float* W_pd  = (const float*)d_in[13];
    const float* b_pd  = (const float*)d_in[14];
    const float* W_pld = (const float*)d_in[15];
    const float* b_pld = (const float*)d_in[16];
    const float* W_pq  = (const float*)d_in[17];
    const float* b_pq  = (const float*)d_in[18];
    const float* W_pr  = (const float*)d_in[19];
    const float* b_pr  = (const float*)d_in[20];
    const float* attn_W= (const float*)d_in[21];
    float* out = (float*)d_out;

    cudaFuncSetAttribute(drl_main, cudaFuncAttributeMaxDynamicSharedMemorySize,
                         (int)sizeof(SmemLayout));

    precompute_kernel<<<84, 512>>>(W_s, b_s, W_ld, b_ld, W_d, b_d,
                                   W_ih, b_ih, W_hh, b_hh,
                                   W_pd, b_pd, W_pld, b_pld,
                                   W_pq, b_pq, W_pr, b_pr, attn_W);

    drl_main<<<NBLK, NTHR, sizeof(SmemLayout)>>>(stat, dyn, mark, out);
}

// round 11
// speedup vs baseline: 3.7107x; 1.0311x over previous
#include <cuda_runtime.h>
#include <math.h>

#define H    128
#define SEQ  128
#define BTOT 2048
#define NB   8             // batches per block
#define NBLK (BTOT/NB)     // 256 blocks
#define NTHR 512
#define O5   640           // 512 (W_hh cols) + 128 (W_pq cols), transposed layout

typedef unsigned long long ull;

// ---------------- device-global scratch -------------------------------------
__device__ float  d_Wt[H*O5];
__device__ float4 d_A4[H];
__device__ float  d_cbias[H];
__device__ float  d_aW[H];
__device__ float  d_G2[512*2];
__device__ float  d_gb[512];
__device__ float  d_base[(size_t)BTOT*H*SEQ];   // 128 MiB: t-invariant attention pre-activation

// ---------------- f32x2 packed helpers --------------------------------------
__device__ __forceinline__ ull pack2(float x, float y) {
    ull r; asm("mov.b64 %0, {%1,%2};" : "=l"(r) : "f"(x), "f"(y)); return r;
}
__device__ __forceinline__ ull fma2(ull a, ull b, ull c) {
    ull d; asm("fma.rn.f32x2 %0, %1, %2, %3;" : "=l"(d) : "l"(a), "l"(b), "l"(c)); return d;
}
__device__ __forceinline__ void unpack2(ull p, float& x, float& y) {
    asm("mov.b64 {%0,%1}, %2;" : "=f"(x), "=f"(y) : "l"(p));
}

// ---------------- exact transcendentals (R4-bitwise) ------------------------
__device__ __forceinline__ float exp_acc(float y) {
    const float L2E_HI = 1.44269502162933349609375f;
    const float L2E_LO = 1.9259629911266175e-8f;
    float p  = y * L2E_HI;
    float e  = fmaf(y, L2E_HI, -p);
    float pc = fminf(fmaxf(p, -126.0f), 126.0f);
    float nf = rintf(pc);
    int   ni = (int)nf;
    float f  = (pc - nf) + fmaf(y, L2E_LO, e);
    float r  = 1.5252733e-5f;
    r = fmaf(r, f, 1.5403530e-4f);
    r = fmaf(r, f, 1.3333558e-3f);
    r = fmaf(r, f, 9.6181291e-3f);
    r = fmaf(r, f, 5.5504109e-2f);
    r = fmaf(r, f, 2.4022651e-1f);
    r = fmaf(r, f, 6.9314718e-1f);
    r = fmaf(r, f, 1.0f);
    float sc = __int_as_float((ni + 127) << 23);
    return r * sc;
}
__device__ __forceinline__ float rcp_nr(float d) {
    float r;
    asm("rcp.approx.f32 %0, %1;" : "=f"(r) : "f"(d));
    return r * fmaf(-d, r, 2.0f);
}
__device__ __forceinline__ float tanh_acc(float x) {
    float E = exp_acc(x + x);
    float q = rcp_nr(E + 1.0f);
    return 1.0f - (q + q);
}
__device__ __forceinline__ float sig_acc(float x) {
    return rcp_nr(1.0f + exp_acc(-x));
}
__device__ __forceinline__ float tanh_fast(float x) {
    float y;
    asm("tanh.approx.f32 %0, %1;" : "=f"(y) : "f"(x));
    return y;
}

// ---------------- phase 0: fold affine algebra (fp64) -----------------------
__global__ void precompute_kernel(
    const float* __restrict__ W_s,  const float* __restrict__ b_s,
    const float* __restrict__ W_ld, const float* __restrict__ b_ld,
    const float* __restrict__ W_d,  const float* __restrict__ b_d,
    const float* __restrict__ W_ih, const float* __restrict__ b_ih,
    const float* __restrict__ W_hh, const float* __restrict__ b_hh,
    const float* __restrict__ W_pd, const float* __restrict__ b_pd,
    const float* __restrict__ W_pld,const float* __restrict__ b_pld,
    const float* __restrict__ W_pq, const float* __restrict__ b_pq,
    const float* __restrict__ W_pr, const float* __restrict__ b_pr,
    const float* __restrict__ attn_W)
{
    int tid  = blockIdx.x * blockDim.x + threadIdx.x;
    int nthr = gridDim.x * blockDim.x;

    for (int idx = tid; idx < H*O5; idx += nthr) {
        int k = idx / O5, o = idx % O5;
        d_Wt[idx] = (o < 512) ? W_hh[o*H + k] : W_pq[(o-512)*H + k];
    }
    for (int h = tid; h < H; h += nthr) {
        double ms0=0, ms1=0, wld=0, wd=0, bb=0;
        for (int k = 0; k < H; k++) {
            double wpr  = (double)W_pr [h*H+k];
            double wpld = (double)W_pld[h*H+k];
            double wpd  = (double)W_pd [h*H+k];
            ms0 += wpr  * (double)W_s[k*2+0];
            ms1 += wpr  * (double)W_s[k*2+1];
            wld += wpld * ((double)W_ld[k*2+0] + (double)W_ld[k*2+1]);
            wd  += wpd  * ((double)W_d [k*2+0] + (double)W_d [k*2+1]);
            bb  += wpr*(double)b_s[k] + wpld*(double)b_ld[k] + wpd*(double)b_d[k];
        }
        bb += (double)b_pr[h] + (double)b_pld[h] + (double)b_pd[h] + (double)b_pq[h];
        d_A4[h]    = make_float4((float)ms0, (float)ms1, (float)wld, (float)wd);
        d_cbias[h] = (float)bb;
        d_aW[h]    = attn_W[h];
    }
    for (int o = tid; o < 512; o += nthr) {
        double g0=0, g1=0, gb=0;
        for (int k = 0; k < H; k++) {
            double w = (double)W_ih[o*H+k];
            g0 += w * (double)W_s[k*2+0];
            g1 += w * (double)W_s[k*2+1];
            gb += w * (double)b_s[k];
        }
        d_G2[o*2+0] = (float)g0; d_G2[o*2+1] = (float)g1;
        d_gb[o]     = (float)(gb + (double)b_ih[o] + (double)b_hh[o]);
    }
}

// ---------------- phase 0b: t-invariant attention pre-activation ------------
__global__ void precompute_base(const float* __restrict__ stat,
                                const float* __restrict__ dyn)
{
    const int b   = blockIdx.x;
    const int tid = threadIdx.x;
    __shared__ float4 us[SEQ];
    __shared__ float4 a4s[H];
    for (int s = tid; s < SEQ; s += 256) {
        int g = b * (2*SEQ);
        float s0 = stat[g + s];
        float s1 = stat[g + SEQ + s];
        float ld = dyn [g + s];
        float dm = dyn [g + SEQ + s];
        us[s] = make_float4(s0, s1, ld - dm, dm);
    }
    for (int i = tid; i < H; i += 256) a4s[i] = d_A4[i];
    __syncthreads();
    float* bp = d_base + (size_t)b * H * SEQ;
    for (int idx = tid; idx < H*SEQ; idx += 256) {
        int s = idx & 127, hh = idx >> 7;
        float4 a = a4s[hh];
        float4 u = us[s];
        bp[idx] = fmaf(a.x,u.x, fmaf(a.y,u.y, fmaf(a.z,u.z, a.w*u.w)));
    }
}

// ---------------- main kernel ------------------------------------------------
struct SmemLayout {
    float4 u[NB][SEQ];       // 16KB (for exact pass + v update)
    float4 A4[H];            //  2KB (exact pass)
    float  ht[H*8];          //  4KB  ht[k*8+b]  (transposed h)
    float  ct[H*8];          //  4KB  ct[j*8+b]
    float2 qa[NB][H];        //  8KB  {q + cbias, aW}
    float  gt[512*9];        // 18KB  gt[o*9+b]  (pad 9: conflict-light)
    float  G2[512][2];       //  4KB
    float  gb[512];          //  2KB
    float  cbias[H];
    float  aW[H];
    float2 v[NB];
    float  red_m [NB][2];
    int    red_mi[NB][2];
    float  red_ds[NB][2];
};

extern __shared__ char smem_raw[];

__global__ void __launch_bounds__(NTHR, 2)
drl_main(const float* __restrict__ stat, const float* __restrict__ dyn,
         const float* __restrict__ mark, float* __restrict__ out)
{
    SmemLayout& sm = *reinterpret_cast<SmemLayout*>(smem_raw);
    const int tid = threadIdx.x;
    const int b0  = blockIdx.x * NB;

    for (int i = tid; i < H; i += NTHR) {
        sm.A4[i]    = d_A4[i];
        sm.cbias[i] = d_cbias[i];
        sm.aW[i]    = d_aW[i];
    }
    for (int i = tid; i < 512; i += NTHR) {
        sm.G2[i][0] = d_G2[i*2+0];
        sm.G2[i][1] = d_G2[i*2+1];
        sm.gb[i]    = d_gb[i];
    }
    for (int idx = tid; idx < NB*SEQ; idx += NTHR) {
        int b = idx >> 7, s = idx & 127;
        int g = (b0 + b) * (2*SEQ);
        float s0 = stat[g + s];
        float s1 = stat[g + SEQ + s];
        float ld = dyn [g + s];
        float dm = dyn [g + SEQ + s];
        sm.u[b][s] = make_float4(s0, s1, ld - dm, dm);
    }
    for (int idx = tid; idx < H*8; idx += NTHR) {
        sm.ht[idx] = 0.f;
        sm.ct[idx] = 0.f;
    }
    __syncthreads();
    if (tid < NB) sm.v[tid] = make_float2(sm.u[tid][0].x, sm.u[tid][0].y);
    if (blockIdx.x == 0 && tid == 0) out[2*BTOT*SEQ] = mark[0];
    __syncthreads();

    const int o    = tid;
    const int o2   = tid & 127;
    const int bg   = tid >> 7;     // GEMM2 batch group (2 batches each)
    const int warp = tid >> 5;
    const int lane = tid & 31;
    const int ab   = warp >> 1;    // attention batch
    const int ah   = warp & 1;     // attention s-half
    const float NEG_INF = __int_as_float(0xff800000);
    const float MARGIN  = 0.012f;

    for (int t = 0; t < SEQ; t++) {
        // ---- GEMM1 (f32x2 packed over batch pairs; per-batch chain R4-bitwise) ----
        {
            float a0[NB];
            float g0 = sm.G2[o][0], g1 = sm.G2[o][1], gbv = sm.gb[o];
            #pragma unroll
            for (int i = 0; i < NB; i++) {
                float2 vv = sm.v[i];
                a0[i] = fmaf(g0, vv.x, fmaf(g1, vv.y, gbv));
            }
            ull ap[4];
            #pragma unroll
            for (int p = 0; p < 4; p++) ap[p] = pack2(a0[2*p], a0[2*p+1]);

            const float* wt = d_Wt + o;
            #pragma unroll 4
            for (int k = 0; k < H; k += 4) {
                float w0 = wt[(k+0)*O5];
                float w1 = wt[(k+1)*O5];
                float w2 = wt[(k+2)*O5];
                float w3 = wt[(k+3)*O5];
                ull wp[4] = { pack2(w0,w0), pack2(w1,w1), pack2(w2,w2), pack2(w3,w3) };
                #pragma unroll
                for (int kk = 0; kk < 4; kk++) {
                    ulonglong2 hA = *reinterpret_cast<const ulonglong2*>(&sm.ht[(k+kk)*8]);
                    ulonglong2 hB = *reinterpret_cast<const ulonglong2*>(&sm.ht[(k+kk)*8+4]);
                    ap[0] = fma2(wp[kk], hA.x, ap[0]);
                    ap[1] = fma2(wp[kk], hA.y, ap[1]);
                    ap[2] = fma2(wp[kk], hB.x, ap[2]);
                    ap[3] = fma2(wp[kk], hB.y, ap[3]);
                }
            }
            #pragma unroll
            for (int p = 0; p < 4; p++) {
                float x, y;
                unpack2(ap[p], x, y);
                sm.gt[o*9 + 2*p    ] = x;
                sm.gt[o*9 + 2*p + 1] = y;
            }
        }
        __syncthreads();

        // ---- LSTM pointwise (R4-bitwise math, transposed addressing) ----
        #pragma unroll
        for (int r = 0; r < (NB*H)/NTHR; r++) {
            int idx = tid + r*NTHR;
            int b = idx & 7, j = idx >> 3;
            float gi = sm.gt[(j      )*9 + b];
            float gf = sm.gt[(j + 128)*9 + b];
            float gg = sm.gt[(j + 256)*9 + b];
            float go = sm.gt[(j + 384)*9 + b];
            float c2 = sig_acc(gf) * sm.ct[j*8+b] + sig_acc(gi) * tanh_acc(gg);
            float h2 = sig_acc(go) * tanh_acc(c2);
            sm.ct[j*8+b] = c2;
            sm.ht[j*8+b] = h2;
        }
        __syncthreads();

        // ---- GEMM2 (f32x2 packed over the 2 batches; per-batch chain R4-bitwise) ----
        {
            float cb = sm.cbias[o2];
            ull acc2 = pack2(cb, cb);
            const float* wt = d_Wt + 512 + o2;
            #pragma unroll 4
            for (int k = 0; k < H; k += 4) {
                float w0 = wt[(k+0)*O5];
                float w1 = wt[(k+1)*O5];
                float w2 = wt[(k+2)*O5];
                float w3 = wt[(k+3)*O5];
                ull h0 = *reinterpret_cast<const ull*>(&sm.ht[(k+0)*8 + bg*2]);
                ull h1 = *reinterpret_cast<const ull*>(&sm.ht[(k+1)*8 + bg*2]);
                ull h2 = *reinterpret_cast<const ull*>(&sm.ht[(k+2)*8 + bg*2]);
                ull h3 = *reinterpret_cast<const ull*>(&sm.ht[(k+3)*8 + bg*2]);
                acc2 = fma2(pack2(w0,w0), h0, acc2);
                acc2 = fma2(pack2(w1,w1), h1, acc2);
                acc2 = fma2(pack2(w2,w2), h2, acc2);
                acc2 = fma2(pack2(w3,w3), h3, acc2);
            }
            float qx, qy;
            unpack2(acc2, qx, qy);
            float aw = sm.aW[o2];
            sm.qa[bg*2    ][o2] = make_float2(qx, aw);
            sm.qa[bg*2 + 1][o2] = make_float2(qy, aw);
        }
        __syncthreads();

        // ---- attention: cheap pass from precomputed base + exact candidates ----
        {
            const int b     = ab;
            const int sbase = ah*64 + lane*2;
            const float* bp = d_base + ((size_t)(b0 + b) * H) * SEQ + sbase;
            float c0 = 0.f, c1 = 0.f;
            #pragma unroll 8
            for (int hh = 0; hh < H; hh++) {
                float2 bs = *reinterpret_cast<const float2*>(bp + hh*SEQ);
                float2 qa = sm.qa[b][hh];
                c0 = fmaf(qa.y, tanh_fast(bs.x + qa.x), c0);
                c1 = fmaf(qa.y, tanh_fast(bs.y + qa.x), c1);
            }
            if (ah == 0 && lane == 0) c0 = NEG_INF;   // masked s=0

            float cm = fmaxf(c0, c1);
            #pragma unroll
            for (int off = 16; off; off >>= 1)
                cm = fmaxf(cm, __shfl_xor_sync(0xffffffffu, cm, off));

            unsigned bal0 = __ballot_sync(0xffffffffu, c0 >= cm - MARGIN);
            unsigned bal1 = __ballot_sync(0xffffffffu, c1 >= cm - MARGIN);

            // exact recompute (R4-bitwise z chain, fp64 warp tree)
            #pragma unroll
            for (int j = 0; j < 2; j++) {
                unsigned msk = j ? bal1 : bal0;
                while (msk) {
                    int sl = __ffs(msk) - 1;
                    msk &= msk - 1;
                    int s = ah*64 + sl*2 + j;
                    float4 us = sm.u[b][s];
                    double p = 0.0;
                    #pragma unroll
                    for (int r = 0; r < 4; r++) {
                        int hh = lane + r*32;
                        float4 a  = sm.A4[hh];
                        float2 qa = sm.qa[b][hh];
                        float z = fmaf(a.x,us.x, fmaf(a.y,us.y, fmaf(a.z,us.z, fmaf(a.w,us.w, qa.x))));
                        p += (double)(qa.y * tanh_acc(z));
                    }
                    #pragma unroll
                    for (int off = 16; off; off >>= 1)
                        p += __shfl_xor_sync(0xffffffffu, p, off);
                    if (lane == sl) { if (j) c1 = (float)p; else c0 = (float)p; }
                }
            }

            float aq0 = c0 + 10000.0f;
            float aq1 = c1 + 10000.0f;

            float m  = aq0;
            int   mi = sbase;
            if (aq1 > m) { m = aq1; mi = sbase + 1; }
            #pragma unroll
            for (int off = 16; off; off >>= 1) {
                float om = __shfl_xor_sync(0xffffffffu, m,  off);
                int   oi = __shfl_xor_sync(0xffffffffu, mi, off);
                if (om > m || (om == m && oi < mi)) { m = om; mi = oi; }
            }
            float d0 = aq0 - m, d1 = aq1 - m;
            float dsum = ((d0 == NEG_INF) ? 0.f : exp_acc(d0))
                       + ((d1 == NEG_INF) ? 0.f : exp_acc(d1));
            #pragma unroll
            for (int off = 16; off; off >>= 1)
                dsum += __shfl_xor_sync(0xffffffffu, dsum, off);

            if (lane == 0) {
                sm.red_m [b][ah] = m;
                sm.red_mi[b][ah] = mi;
                sm.red_ds[b][ah] = dsum;
            }
        }
        __syncthreads();

        // ---- combine halves, emit outputs, update dec ----
        if (tid < NB) {
            const int b = tid;
            float m0 = sm.red_m[b][0], m1 = sm.red_m[b][1];
            int  mi0 = sm.red_mi[b][0], mi1 = sm.red_mi[b][1];
            float dd0 = sm.red_ds[b][0], dd1 = sm.red_ds[b][1];
            float m; int mi;
            if (m1 > m0 || (m1 == m0 && mi1 < mi0)) { m = m1; mi = mi1; }
            else                                    { m = m0; mi = mi0; }
            float dsum = dd0 * exp_acc(m0 - m) + dd1 * exp_acc(m1 - m);
            out[(b0 + b)*SEQ + t]            = (float)mi;
            out[BTOT*SEQ + (b0 + b)*SEQ + t] = -logf(dsum);
            sm.v[b] = make_float2(sm.u[b][mi].x, sm.u[b][mi].y);
        }
        __syncthreads();
    }
}

// ---------------- launch --------------------------------------------------
extern "C" void kernel_launch(void* const* d_in, const int* in_sizes, int n_in,
                              void* d_out, int out_size)
{
    (void)in_sizes; (void)n_in; (void)out_size;
    const float* stat  = (const float*)d_in[0];
    const float* dyn   = (const float*)d_in[1];
    const float* mark  = (const float*)d_in[2];
    const float* W_s   = (const float*)d_in[3];
    const float* b_s   = (const float*)d_in[4];
    const float* W_ld  = (const float*)d_in[5];
    const float* b_ld  = (const float*)d_in[6];
    const float* W_d   = (const float*)d_in[7];
    const float* b_d   = (const float*)d_in[8];
    const float* W_ih  = (const float*)d_in[9];
    const float* b_ih  = (const float*)d_in[10];
    const float* W_hh  = (const float*)d_in[11];
    const float* b_hh  = (const float*)d_in[12];
    const float* W_pd  = (const float*)d_in[13];
    const float* b_pd  = (const float*)d_in[14];
    const float* W_pld = (const float*)d_in[15];
    const float* b_pld = (const float*)d_in[16];
    const float* W_pq  = (const float*)d_in[17];
    const float* b_pq  = (const float*)d_in[18];
    const float* W_pr  = (const float*)d_in[19];
    const float* b_pr  = (const float*)d_in[20];
    const float* attn_W= (const float*)d_in[21];
    float* out = (float*)d_out;

    cudaFuncSetAttribute(drl_main, cudaFuncAttributeMaxDynamicSharedMemorySize,
                         (int)sizeof(SmemLayout));

    precompute_kernel<<<84, 512>>>(W_s, b_s, W_ld, b_ld, W_d, b_d,
                                   W_ih, b_ih, W_hh, b_hh,
                                   W_pd, b_pd, W_pld, b_pld,
                                   W_pq, b_pq, W_pr, b_pr, attn_W);

    precompute_base<<<BTOT, 256>>>(stat, dyn);

    drl_main<<<NBLK, NTHR, sizeof(SmemLayout)>>>(stat, dyn, mark, out);
}